// round 16
// baseline (speedup 1.0000x reference)
#include <cuda_runtime.h>
#include <cstdint>
#include <math.h>

#define BB 128
#define NN 1000
#define DD 196
#define KK 48
#define NC 64            // top-NC of x used only to build the probe ladder
#define NWARPS 32
#define THREADS (NWARPS * 32)
#define NPROBE 16
#define PLO 40           // probe ladder covers x ranks 40..55 (0-indexed, among all 196)

__device__ __forceinline__ unsigned f2key(float v) {
    unsigned u = __float_as_uint(v);
    return u ^ ((unsigned)((int)u >> 31) | 0x80000000u);
}

__global__ __launch_bounds__(THREADS, 1)
void ptk_kernel(const float* __restrict__ x,
                const float* __restrict__ noise,
                const float* __restrict__ sigma_p,
                float* __restrict__ out)
{
    __shared__ int acc[KK * DD];        // 37632 B
    __shared__ short cidx[NC];          // top-NC column ids of x (ladder build only)
    __shared__ __align__(16) unsigned probeT[NPROBE]; // x-keys at ranks PLO..PLO+15

    const int b = blockIdx.x, tid = threadIdx.x, lane = tid & 31, warp = tid >> 5;
    const unsigned lt = (1u << lane) - 1u;
    const unsigned FULL = 0xffffffffu;

    for (int i = tid; i < KK * DD; i += THREADS) acc[i] = 0;

    // ---- per-b precompute (warp 0): top-NC x columns -> rank ladder 40..55 ----
    if (warp == 0) {
        unsigned key[7];
#pragma unroll
        for (int j = 0; j < 7; ++j) {
            int d = j * 32 + lane;
            key[j] = (d < DD) ? f2key(x[b * DD + d]) : 0u;
        }
        unsigned prefix = 0;
        for (int bit = 31; bit >= 0; --bit) {
            unsigned t = prefix | (1u << bit);
            int c = 0;
#pragma unroll
            for (int j = 0; j < 7; ++j) c += (key[j] >= t);
            c = __reduce_add_sync(FULL, c);
            if (c >= NC) { prefix = t; if (c == NC) break; }
        }
        int cgt = 0;
#pragma unroll
        for (int j = 0; j < 7; ++j) cgt += (key[j] > prefix);
        cgt = __reduce_add_sync(FULL, cgt);
        int rem = NC - cgt;
        int cb = 0, eqb = 0;
#pragma unroll
        for (int j = 0; j < 7; ++j) {
            int d = j * 32 + lane;
            bool valid = d < DD;
            bool gt = key[j] > prefix;
            bool eq = valid && (key[j] == prefix);
            unsigned be = __ballot_sync(FULL, eq);
            bool sel = gt || (eq && (eqb + __popc(be & lt)) < rem);
            unsigned bs = __ballot_sync(FULL, sel);
            if (sel) cidx[cb + __popc(bs & lt)] = (short)d;
            eqb += __popc(be); cb += __popc(bs);
        }
        __syncwarp();

        // rank the 64 top x-keys (desc key, asc slot tiebreak); ranks < 64 among all 196
        const float* xbp = x + b * DD;
        unsigned a0 = f2key(xbp[cidx[lane]]);       // slot = lane
        unsigned a1 = f2key(xbp[cidx[32 + lane]]);  // slot = lane + 32
        int r0 = 0, r1 = 0;
        for (int src = 0; src < 32; ++src) {
            unsigned b0 = __shfl_sync(FULL, a0, src);
            unsigned b1 = __shfl_sync(FULL, a1, src);
            r0 += (b0 > a0) + (b1 > a0) + ((b0 == a0) && (src < lane));
            r1 += (b0 > a1) + (b1 > a1) + (b0 == a1) + ((b1 == a1) && (src < lane));
        }
        if (r0 >= PLO && r0 < PLO + NPROBE) probeT[r0 - PLO] = a0;
        if (r1 >= PLO && r1 < PLO + NPROBE) probeT[r1 - PLO] = a1;
    }
    __syncthreads();

    const float sigma = sigma_p ? *sigma_p : 0.05f;

    // coalesced per-lane x values: d = j*32 + lane
    float xv[7];
#pragma unroll
    for (int j = 0; j < 7; ++j) {
        int d = j * 32 + lane;
        xv[j] = (d < DD) ? x[b * DD + d] : 0.0f;
    }
    const int d6ok = (6 * 32 + lane) < DD;       // j=6 valid only for lane<4
    const int d6 = d6ok ? (6 * 32 + lane) : (DD - 1);  // clamped load address

    // level-1 probes in registers: ladder indices 0,4,8,12 (ranks 40,44,48,52)
    const unsigned fl0 = probeT[0], fl1 = probeT[4], fl2 = probeT[8], fl3 = probeT[12];

    const float* nbase = noise + (size_t)b * NN * DD;

    for (int n = warp; n < NN; n += NWARPS) {
        const float* row = nbase + (size_t)n * DD;

        // 7 coalesced loads -> keys (key[6]=0 on invalid lanes)
        unsigned key[7];
#pragma unroll
        for (int j = 0; j < 6; ++j)
            key[j] = f2key(fmaf(sigma, row[j * 32 + lane], xv[j]));
        key[6] = d6ok ? f2key(fmaf(sigma, row[d6], xv[6])) : 0u;

        // ---- level-1: 4 packed probe counts over 7 keys, one REDUX ----
        unsigned pc = 0;
#pragma unroll
        for (int j = 0; j < 7; ++j) {
            unsigned k = key[j];
            pc += (unsigned)(k >= fl0)
                | ((unsigned)(k >= fl1) << 8)
                | ((unsigned)(k >= fl2) << 16)
                | ((unsigned)(k >= fl3) << 24);
        }
        pc = __reduce_add_sync(FULL, pc);

        unsigned vT = 0u;
        bool have = false, needfull = false;

        unsigned e = __vcmpeq4(pc, 0x30303030u);   // bytes with count == 48
        unsigned g = __vcmpgeu4(pc, 0x30303030u);  // bytes with count >= 48

        if (e != 0u) {
            int by = (__ffs(e) - 1) >> 3;
            vT = probeT[4 * by];
            have = true;
        } else if (g != 0u && (g & 0xffu) != 0u) {
            needfull = true;                       // c(rank40) > 48: above ladder
        } else {
            int p; bool haveUpper;
            if (g != 0u) { int by = (__ffs(g) - 1) >> 3; p = 4 * (by - 1); haveUpper = true; }
            else         { p = 12; haveUpper = false; }

            // level-2: 3 interior probes in one packed REDUX
            unsigned T1 = probeT[p + 1], T2 = probeT[p + 2], T3 = probeT[p + 3];
            unsigned sc = 0;
#pragma unroll
            for (int j = 0; j < 7; ++j) {
                unsigned k = key[j];
                sc += (unsigned)(k >= T1)
                    | ((unsigned)(k >= T2) << 8)
                    | ((unsigned)(k >= T3) << 16);
            }
            sc = __reduce_add_sync(FULL, sc);
            int c1 = sc & 255, c2 = (sc >> 8) & 255, c3 = (int)((sc >> 16) & 255);

            unsigned lo = 0u, hi = 0u; bool bisect = false;
            if      (c1 == KK) { vT = T1; have = true; }
            else if (c1 >  KK) { lo = T1; hi = probeT[p]; bisect = true; }
            else if (c2 == KK) { vT = T2; have = true; }
            else if (c2 >  KK) { lo = T2; hi = T1; bisect = true; }
            else if (c3 == KK) { vT = T3; have = true; }
            else if (c3 >  KK) { lo = T3; hi = T2; bisect = true; }
            else if (haveUpper) { lo = probeT[p + 4]; hi = T3; bisect = true; }
            else needfull = true;                  // below ladder bottom

            if (bisect) {
                // c(lo) > 48, c(hi) < 48, lo < hi in key space
                for (int it = 0; it < 8; ++it) {
                    unsigned gap = hi - lo;
                    if (gap <= 1u) break;
                    unsigned qq = gap >> 2;
                    unsigned m1, m2, m3;
                    if (gap >= 4u) { m1 = lo + qq; m2 = lo + 2 * qq; m3 = hi - qq; }
                    else           { m1 = lo + (gap >> 1); m2 = m1; m3 = m1; }
                    unsigned pp = 0;
#pragma unroll
                    for (int j = 0; j < 7; ++j) {
                        unsigned k = key[j];
                        pp += (unsigned)(k >= m1)
                            | ((unsigned)(k >= m2) << 8)
                            | ((unsigned)(k >= m3) << 16);
                    }
                    pp = __reduce_add_sync(FULL, pp);
                    int b1 = pp & 255, b2 = (pp >> 8) & 255, b3 = (int)((pp >> 16) & 255);
                    if      (b3 == KK) { vT = m3; have = true; break; }
                    else if (b2 == KK) { vT = m2; have = true; break; }
                    else if (b1 == KK) { vT = m1; have = true; break; }
                    else if (b3 > KK)  lo = m3;
                    else if (b2 > KK)  { lo = m2; hi = m3; }
                    else if (b1 > KK)  { lo = m1; hi = m2; }
                    else               hi = m1;
                }
                if (!have) needfull = true;
            }
        }

        if (!needfull) {
            // HIT path: c(vT)==48 over ALL keys -> set {k >= vT} is top-48, no ties
            int selb = 0;
#pragma unroll
            for (int j = 0; j < 7; ++j) {
                bool sel = (key[j] >= vT);
                unsigned bs = __ballot_sync(FULL, sel);
                if (sel) atomicAdd(&acc[(selb + __popc(bs & lt)) * DD + (j * 32 + lane)], 1);
                selb += __popc(bs);
            }
        } else {
            // exact 1-bit radix over the 7 register keys (rare), then tie-aware scatter
            unsigned prefix = 0;
            for (int bit = 31; bit >= 0; --bit) {
                unsigned t = prefix | (1u << bit);
                int c = 0;
#pragma unroll
                for (int j = 0; j < 7; ++j) c += (key[j] >= t);
                c = __reduce_add_sync(FULL, c);
                if (c >= KK) { prefix = t; if (c == KK) break; }
            }
            vT = prefix;

            int cgt = 0;
#pragma unroll
            for (int j = 0; j < 7; ++j) cgt += (key[j] > vT);
            cgt = __reduce_add_sync(FULL, cgt);
            int rem = KK - cgt;

            int selb = 0, eqb = 0;
#pragma unroll
            for (int j = 0; j < 7; ++j) {
                bool gt = key[j] > vT;
                bool eq = (key[j] == vT);
                unsigned be = __ballot_sync(FULL, eq);
                bool sel = gt || (eq && (eqb + __popc(be & lt)) < rem);
                unsigned bs = __ballot_sync(FULL, sel);
                if (sel) atomicAdd(&acc[(selb + __popc(bs & lt)) * DD + (j * 32 + lane)], 1);
                eqb += __popc(be);
                selb += __popc(bs);
            }
        }
    }

    __syncthreads();

    const float inv = 1.0f / (float)NN;
    float* ob = out + (size_t)b * KK * DD;
    for (int i = tid; i < KK * DD; i += THREADS)
        ob[i] = (float)acc[i] * inv;
}

extern "C" void kernel_launch(void* const* d_in, const int* in_sizes, int n_in,
                              void* d_out, int out_size)
{
    const float* x     = nullptr;
    const float* noise = nullptr;
    const float* sigma = nullptr;
    for (int i = 0; i < n_in; ++i) {
        if      (in_sizes[i] == BB * DD)      x     = (const float*)d_in[i];
        else if (in_sizes[i] == BB * NN * DD) noise = (const float*)d_in[i];
        else if (in_sizes[i] == 1)            sigma = (const float*)d_in[i];
    }
    ptk_kernel<<<BB, THREADS>>>(x, noise, sigma, (float*)d_out);
}

// round 17
// speedup vs baseline: 1.7547x; 1.7547x over previous
#include <cuda_runtime.h>
#include <cstdint>
#include <math.h>

#define BB 128
#define NN 1000
#define DD 196
#define KK 48
#define NC 64            // candidate columns (top-NC of x per batch row)
#define NO (DD - NC)     // 132 other columns
#define NWARPS 32
#define THREADS (NWARPS * 32)
#define NPROBE 16
#define PLO 40           // probe ladder covers x ranks 40..55 (0-indexed)

__device__ __forceinline__ unsigned f2key(float v) {
    unsigned u = __float_as_uint(v);
    return u ^ ((unsigned)((int)u >> 31) | 0x80000000u);
}

// Exact full-width fallback: top-KK of all 196 perturbed values, d-ascending ranks.
__device__ __noinline__ void fallback_select(const float* __restrict__ row,
                                             const float* __restrict__ xb,
                                             float sigma, int* acc,
                                             int lane, unsigned lt)
{
    const unsigned FULL = 0xffffffffu;
    unsigned key[7];
#pragma unroll
    for (int j = 0; j < 7; ++j) {
        int d = j * 32 + lane;
        key[j] = (d < DD) ? f2key(fmaf(sigma, row[d], xb[d])) : 0u;
    }
    unsigned prefix = 0;
    for (int bit = 31; bit >= 0; --bit) {
        unsigned t = prefix | (1u << bit);
        int c = 0;
#pragma unroll
        for (int j = 0; j < 7; ++j) c += (key[j] >= t);
        c = __reduce_add_sync(FULL, c);
        if (c >= KK) { prefix = t; if (c == KK) break; }
    }
    int cgt = 0;
#pragma unroll
    for (int j = 0; j < 7; ++j) cgt += (key[j] > prefix);
    cgt = __reduce_add_sync(FULL, cgt);
    int rem = KK - cgt;
    int selb = 0, eqb = 0;
#pragma unroll
    for (int j = 0; j < 7; ++j) {
        bool gt = key[j] > prefix;
        bool eq = (key[j] == prefix);
        unsigned be = __ballot_sync(FULL, eq);
        bool sel = gt || (eq && (eqb + __popc(be & lt)) < rem);
        unsigned bs = __ballot_sync(FULL, sel);
        if (sel) atomicAdd(&acc[(selb + __popc(bs & lt)) * DD + (j * 32 + lane)], 1);
        eqb += __popc(be);
        selb += __popc(bs);
    }
}

__global__ __launch_bounds__(THREADS, 1)
void ptk_kernel(const float* __restrict__ x,
                const float* __restrict__ noise,
                const float* __restrict__ sigma_p,
                float* __restrict__ out)
{
    __shared__ int acc[KK * DD];        // 37632 B
    __shared__ short cidx[NC];          // candidate column ids, ascending d
    __shared__ short oidx[NO];          // other column ids, ascending d
    __shared__ __align__(16) unsigned probeT[NPROBE]; // x-keys at ranks PLO..PLO+15

    const int b = blockIdx.x, tid = threadIdx.x, lane = tid & 31, warp = tid >> 5;
    const unsigned lt = (1u << lane) - 1u;
    const unsigned FULL = 0xffffffffu;

    for (int i = tid; i < KK * DD; i += THREADS) acc[i] = 0;

    // ---- per-b precompute (warp 0): exact top-NC columns of x + probe ladder ----
    if (warp == 0) {
        unsigned key[7];
#pragma unroll
        for (int j = 0; j < 7; ++j) {
            int d = j * 32 + lane;
            key[j] = (d < DD) ? f2key(x[b * DD + d]) : 0u;
        }
        unsigned prefix = 0;
        for (int bit = 31; bit >= 0; --bit) {
            unsigned t = prefix | (1u << bit);
            int c = 0;
#pragma unroll
            for (int j = 0; j < 7; ++j) c += (key[j] >= t);
            c = __reduce_add_sync(FULL, c);
            if (c >= NC) { prefix = t; if (c == NC) break; }
        }
        int cgt = 0;
#pragma unroll
        for (int j = 0; j < 7; ++j) cgt += (key[j] > prefix);
        cgt = __reduce_add_sync(FULL, cgt);
        int rem = NC - cgt;
        int cb = 0, ob = 0, eqb = 0;
#pragma unroll
        for (int j = 0; j < 7; ++j) {
            int d = j * 32 + lane;
            bool valid = d < DD;
            bool gt = key[j] > prefix;
            bool eq = valid && (key[j] == prefix);
            unsigned be = __ballot_sync(FULL, eq);
            bool sel = gt || (eq && (eqb + __popc(be & lt)) < rem);
            unsigned bs = __ballot_sync(FULL, sel);
            unsigned bo = __ballot_sync(FULL, valid && !sel);
            if (sel)        cidx[cb + __popc(bs & lt)] = (short)d;
            else if (valid) oidx[ob + __popc(bo & lt)] = (short)d;
            eqb += __popc(be); cb += __popc(bs); ob += __popc(bo);
        }
        __syncwarp();

        // probe ladder: rank the 64 candidate x-keys (desc key, asc slot tiebreak)
        const float* xbp = x + b * DD;
        unsigned a0 = f2key(xbp[cidx[lane]]);       // slot = lane
        unsigned a1 = f2key(xbp[cidx[32 + lane]]);  // slot = lane + 32
        int r0 = 0, r1 = 0;
        for (int src = 0; src < 32; ++src) {
            unsigned b0 = __shfl_sync(FULL, a0, src);
            unsigned b1 = __shfl_sync(FULL, a1, src);
            r0 += (b0 > a0) + (b1 > a0) + ((b0 == a0) && (src < lane));
            r1 += (b0 > a1) + (b1 > a1) + (b0 == a1) + ((b1 == a1) && (src < lane));
        }
        if (r0 >= PLO && r0 < PLO + NPROBE) probeT[r0 - PLO] = a0;
        if (r1 >= PLO && r1 < PLO + NPROBE) probeT[r1 - PLO] = a1;
    }
    __syncthreads();

    const float sigma = sigma_p ? *sigma_p : 0.05f;
    const float* xb = x + b * DD;

    // per-lane static gather indices + x values
    const int dC0 = cidx[lane];
    const int dC1 = cidx[32 + lane];
    const float xC0 = xb[dC0];
    const float xC1 = xb[dC1];
    int dO[5]; float xO[5];
#pragma unroll
    for (int j = 0; j < 5; ++j) {
        int p = j * 32 + lane;
        if (p < NO) { dO[j] = oidx[p]; xO[j] = xb[dO[j]]; }
        else        { dO[j] = 0;       xO[j] = -INFINITY; }
    }

    // level-1 probes hoisted into registers: CONSECUTIVE ranks 46,47,48,49
    // (ladder indices 6,7,8,9) — centered on the c==48 crossing point.
    const unsigned fl0 = probeT[6], fl1 = probeT[7], fl2 = probeT[8], fl3 = probeT[9];

    const float* nbase = noise + (size_t)b * NN * DD;

    for (int n = warp; n < NN; n += NWARPS) {
        const float* row = nbase + (size_t)n * DD;

        // candidate keys + non-candidate max (tree)
        unsigned k0 = f2key(fmaf(sigma, row[dC0], xC0));
        unsigned k1 = f2key(fmaf(sigma, row[dC1], xC1));
        float f0 = fmaf(sigma, row[dO[0]], xO[0]);
        float f1 = fmaf(sigma, row[dO[1]], xO[1]);
        float f2 = fmaf(sigma, row[dO[2]], xO[2]);
        float f3 = fmaf(sigma, row[dO[3]], xO[3]);
        float f4 = fmaf(sigma, row[dO[4]], xO[4]);
        float mo = fmaxf(fmaxf(fmaxf(f0, f1), fmaxf(f2, f3)), f4);

        // ---- level-1: 4 consecutive-rank probe counts in one packed REDUX ----
        unsigned pc = (unsigned)((k0 >= fl0) + (k1 >= fl0))
                    | ((unsigned)((k0 >= fl1) + (k1 >= fl1)) << 8)
                    | ((unsigned)((k0 >= fl2) + (k1 >= fl2)) << 16)
                    | ((unsigned)((k0 >= fl3) + (k1 >= fl3)) << 24);
        unsigned moK = f2key(mo);
        pc  = __reduce_add_sync(FULL, pc);
        moK = __reduce_max_sync(FULL, moK);

        unsigned vT = 0u;
        bool have = false, needfull = false, dobisect = false;
        unsigned lo = 0u, hi = 0u;

        unsigned e = __vcmpeq4(pc, 0x30303030u);   // bytes with count == 48
        unsigned g = __vcmpgeu4(pc, 0x30303030u);  // bytes with count >= 48

        if (e != 0u) {
            int by = (__ffs(e) - 1) >> 3;
            vT = (by == 0) ? fl0 : (by == 1) ? fl1 : (by == 2) ? fl2 : fl3;
            have = true;
        } else if ((g & 0xffu) != 0u) {
            // c(rank46) > 48: crossing below rank 46 -> probe ranks 42..45
            unsigned T0 = probeT[2], T1 = probeT[3], T2 = probeT[4], T3 = probeT[5];
            unsigned sc = (unsigned)((k0 >= T0) + (k1 >= T0))
                        | ((unsigned)((k0 >= T1) + (k1 >= T1)) << 8)
                        | ((unsigned)((k0 >= T2) + (k1 >= T2)) << 16)
                        | ((unsigned)((k0 >= T3) + (k1 >= T3)) << 24);
            sc = __reduce_add_sync(FULL, sc);
            unsigned e2 = __vcmpeq4(sc, 0x30303030u);
            unsigned g2 = __vcmpgeu4(sc, 0x30303030u);
            if (e2 != 0u) {
                int by2 = (__ffs(e2) - 1) >> 3;
                vT = probeT[2 + by2];
                have = true;
            } else if ((g2 & 0xffu) != 0u) {
                needfull = true;                   // c(rank42) > 48: above sub-ladder
            } else if (g2 != 0u) {
                int by2 = (__ffs(g2) - 1) >> 3;    // >=1; prior byte < 48
                lo = probeT[2 + by2]; hi = probeT[1 + by2]; dobisect = true;
            } else {
                lo = fl0; hi = probeT[5]; dobisect = true;   // c45<48<c46
            }
        } else if (g != 0u) {
            // crossing inside 46..49 with a jump (no exact 48)
            int by = (__ffs(g) - 1) >> 3;          // >=1 here (byte0 handled above)
            lo = (by == 1) ? fl1 : (by == 2) ? fl2 : fl3;
            hi = (by == 1) ? fl0 : (by == 2) ? fl1 : fl2;
            dobisect = true;
        } else {
            // c(rank49) < 48: crossing above rank 49 -> probe ranks 50..53
            unsigned T0 = probeT[10], T1 = probeT[11], T2 = probeT[12], T3 = probeT[13];
            unsigned sc = (unsigned)((k0 >= T0) + (k1 >= T0))
                        | ((unsigned)((k0 >= T1) + (k1 >= T1)) << 8)
                        | ((unsigned)((k0 >= T2) + (k1 >= T2)) << 16)
                        | ((unsigned)((k0 >= T3) + (k1 >= T3)) << 24);
            sc = __reduce_add_sync(FULL, sc);
            unsigned e2 = __vcmpeq4(sc, 0x30303030u);
            unsigned g2 = __vcmpgeu4(sc, 0x30303030u);
            if (e2 != 0u) {
                int by2 = (__ffs(e2) - 1) >> 3;
                vT = probeT[10 + by2];
                have = true;
            } else if ((g2 & 0xffu) != 0u) {
                lo = probeT[10]; hi = fl3; dobisect = true;  // c49<48<c50
            } else if (g2 != 0u) {
                int by2 = (__ffs(g2) - 1) >> 3;
                lo = probeT[10 + by2]; hi = probeT[9 + by2]; dobisect = true;
            } else {
                needfull = true;                   // c(rank53) < 48: below sub-ladder
            }
        }

        if (dobisect) {
            // c(lo) > 48, c(hi) < 48, lo < hi in key space
            for (int it = 0; it < 8; ++it) {
                unsigned gap = hi - lo;
                if (gap <= 1u) break;
                unsigned qq = gap >> 2;
                unsigned m1, m2, m3;
                if (gap >= 4u) { m1 = lo + qq; m2 = lo + 2 * qq; m3 = hi - qq; }
                else           { m1 = lo + (gap >> 1); m2 = m1; m3 = m1; }
                unsigned pp = (unsigned)((k0 >= m1) + (k1 >= m1))
                            | ((unsigned)((k0 >= m2) + (k1 >= m2)) << 8)
                            | ((unsigned)((k0 >= m3) + (k1 >= m3)) << 16);
                pp = __reduce_add_sync(FULL, pp);
                int b1 = pp & 255, b2 = (pp >> 8) & 255, b3 = (int)((pp >> 16) & 255);
                if      (b3 == KK) { vT = m3; have = true; break; }
                else if (b2 == KK) { vT = m2; have = true; break; }
                else if (b1 == KK) { vT = m1; have = true; break; }
                else if (b3 > KK)  lo = m3;
                else if (b2 > KK)  { lo = m2; hi = m3; }
                else if (b1 > KK)  { lo = m1; hi = m2; }
                else               hi = m1;
            }
            if (!have) needfull = true;
        }

        if (needfull) {
            // Exact 1-bit radix + full tie-break scatter (rare path)
            unsigned A = __reduce_and_sync(FULL, k0 & k1);
            unsigned O = __reduce_or_sync(FULL, k0 | k1);
            unsigned xr = A ^ O;
            if (xr == 0u) {
                vT = A;
            } else {
                int hb = 31 - __clz(xr);
                unsigned prefix = (hb < 31) ? ((A >> (hb + 1)) << (hb + 1)) : 0u;
                for (int bit = hb; bit >= 0; --bit) {
                    unsigned t = prefix | (1u << bit);
                    int c = (int)(k0 >= t) + (int)(k1 >= t);
                    c = __reduce_add_sync(FULL, c);
                    if (c >= KK) { prefix = t; if (c == KK) break; }
                }
                vT = prefix;
            }

            if (moK >= vT) {
                fallback_select(row, xb, sigma, acc, lane, lt);
            } else {
                int cgt = __reduce_add_sync(FULL, (int)(k0 > vT) + (int)(k1 > vT));
                int rem = KK - cgt;
                bool gt = k0 > vT, eq = (k0 == vT);
                unsigned be = __ballot_sync(FULL, eq);
                bool sel = gt || (eq && (__popc(be & lt)) < rem);
                unsigned bs = __ballot_sync(FULL, sel);
                if (sel) atomicAdd(&acc[(__popc(bs & lt)) * DD + dC0], 1);
                int eqb = __popc(be), selb = __popc(bs);

                gt = k1 > vT; eq = (k1 == vT);
                be = __ballot_sync(FULL, eq);
                sel = gt || (eq && (eqb + __popc(be & lt)) < rem);
                bs = __ballot_sync(FULL, sel);
                if (sel) atomicAdd(&acc[(selb + __popc(bs & lt)) * DD + dC1], 1);
            }
        } else {
            // HIT path: c(vT) == 48 exactly -> selected set is {k >= vT}, no ties
            if (moK >= vT) {
                fallback_select(row, xb, sigma, acc, lane, lt);
            } else {
                bool s0 = (k0 >= vT);
                bool s1 = (k1 >= vT);
                unsigned bs0 = __ballot_sync(FULL, s0);
                unsigned bs1 = __ballot_sync(FULL, s1);
                if (s0) atomicAdd(&acc[(__popc(bs0 & lt)) * DD + dC0], 1);
                if (s1) atomicAdd(&acc[(__popc(bs0) + __popc(bs1 & lt)) * DD + dC1], 1);
            }
        }
    }

    __syncthreads();

    const float inv = 1.0f / (float)NN;
    float* ob = out + (size_t)b * KK * DD;
    for (int i = tid; i < KK * DD; i += THREADS)
        ob[i] = (float)acc[i] * inv;
}

extern "C" void kernel_launch(void* const* d_in, const int* in_sizes, int n_in,
                              void* d_out, int out_size)
{
    const float* x     = nullptr;
    const float* noise = nullptr;
    const float* sigma = nullptr;
    for (int i = 0; i < n_in; ++i) {
        if      (in_sizes[i] == BB * DD)      x     = (const float*)d_in[i];
        else if (in_sizes[i] == BB * NN * DD) noise = (const float*)d_in[i];
        else if (in_sizes[i] == 1)            sigma = (const float*)d_in[i];
    }
    ptk_kernel<<<BB, THREADS>>>(x, noise, sigma, (float*)d_out);
}